// round 1
// baseline (speedup 1.0000x reference)
#include <cuda_runtime.h>
#include <math.h>

// Problem constants
#define NB   2
#define NS   2048
#define NHID 4096
#define NH   32
#define NKV  8
#define HD   128
#define NM   (NB*NS)        // 4096 rows
#define QDIM (NH*HD)        // 4096
#define KVDIM (NKV*HD)      // 1024

// Scratch (device globals: allocation-free rule)
__device__ float g_q[(size_t)NM*QDIM];
__device__ float g_k[(size_t)NM*KVDIM];
__device__ float g_v[(size_t)NM*KVDIM];
__device__ float g_o[(size_t)NM*QDIM];
__device__ float g_cos[NS*(HD/2)];
__device__ float g_sin[NS*(HD/2)];

// ---------------------------------------------------------------------------
// NT SGEMM: C[M,N] = A[M,K] * B[N,K]^T, all row-major. 128x128x16 tile,
// 256 threads, 8x8 per thread.
// ---------------------------------------------------------------------------
__global__ void __launch_bounds__(256, 1) sgemm_nt(
    const float* __restrict__ A, const float* __restrict__ Bm,
    float* __restrict__ C, int M, int N, int K)
{
    __shared__ float As[16][132];
    __shared__ float Bs[16][132];

    const int tid = threadIdx.x;
    const int bm = blockIdx.y << 7;
    const int bn = blockIdx.x << 7;
    const int ty = tid >> 4;
    const int tx = tid & 15;

    float acc[8][8];
    #pragma unroll
    for (int i = 0; i < 8; ++i)
        #pragma unroll
        for (int j = 0; j < 8; ++j) acc[i][j] = 0.f;

    const int lrow = tid >> 2;          // 0..63
    const int lc4  = (tid & 3) << 2;    // 0,4,8,12

    for (int kt = 0; kt < K; kt += 16) {
        #pragma unroll
        for (int half = 0; half < 2; ++half) {
            int row = lrow + half * 64;
            float4 a = *(const float4*)(A + (size_t)(bm + row) * K + kt + lc4);
            As[lc4+0][row] = a.x; As[lc4+1][row] = a.y;
            As[lc4+2][row] = a.z; As[lc4+3][row] = a.w;
            float4 b = *(const float4*)(Bm + (size_t)(bn + row) * K + kt + lc4);
            Bs[lc4+0][row] = b.x; Bs[lc4+1][row] = b.y;
            Bs[lc4+2][row] = b.z; Bs[lc4+3][row] = b.w;
        }
        __syncthreads();

        #pragma unroll
        for (int k = 0; k < 16; ++k) {
            float4 a0 = *(const float4*)&As[k][ty*8];
            float4 a1 = *(const float4*)&As[k][ty*8 + 4];
            float4 b0 = *(const float4*)&Bs[k][tx*8];
            float4 b1 = *(const float4*)&Bs[k][tx*8 + 4];
            float a[8] = {a0.x,a0.y,a0.z,a0.w,a1.x,a1.y,a1.z,a1.w};
            float b[8] = {b0.x,b0.y,b0.z,b0.w,b1.x,b1.y,b1.z,b1.w};
            #pragma unroll
            for (int i = 0; i < 8; ++i)
                #pragma unroll
                for (int j = 0; j < 8; ++j)
                    acc[i][j] = fmaf(a[i], b[j], acc[i][j]);
        }
        __syncthreads();
    }

    #pragma unroll
    for (int i = 0; i < 8; ++i) {
        float* cp = C + (size_t)(bm + ty*8 + i) * N + bn + tx*8;
        *(float4*)(cp)     = make_float4(acc[i][0], acc[i][1], acc[i][2], acc[i][3]);
        *(float4*)(cp + 4) = make_float4(acc[i][4], acc[i][5], acc[i][6], acc[i][7]);
    }
}

// ---------------------------------------------------------------------------
// RoPE table: cos/sin for (pos, i) with inv_freq = 1/10000^(i/64)
// ---------------------------------------------------------------------------
__global__ void rope_table_kernel()
{
    int idx = blockIdx.x * blockDim.x + threadIdx.x;
    if (idx >= NS * 64) return;
    int pos = idx >> 6;
    int i = idx & 63;
    float inv = 1.0f / powf(10000.0f, (float)i / 64.0f);
    float f = (float)pos * inv;
    g_cos[idx] = cosf(f);
    g_sin[idx] = sinf(f);
}

// In-place rotary embedding: pairs (i, i+64) per head
__global__ void rope_apply_kernel(float* __restrict__ X, int nheads)
{
    int idx = blockIdx.x * blockDim.x + threadIdx.x;
    int total = NM * nheads * 64;
    if (idx >= total) return;
    int i = idx & 63;
    int h = (idx >> 6) % nheads;
    int m = idx / (nheads * 64);
    int pos = m & (NS - 1);
    float* p = X + (size_t)m * nheads * HD + h * HD + i;
    float x1 = p[0], x2 = p[64];
    float c = g_cos[pos * 64 + i];
    float s = g_sin[pos * 64 + i];
    p[0]  = x1 * c - x2 * s;
    p[64] = x1 * s + x2 * c;
}

// ---------------------------------------------------------------------------
// Flash attention, fp32, causal, GQA (4 Q-heads per KV head).
// Block = one (batch, head, 64-row q tile). 256 threads (16x16).
// Each thread: 4x4 of the 64x64 score tile, 4 rows x 8 d-cols of output.
// ---------------------------------------------------------------------------
#define QT 64
#define KTL 64
#define PD 132      // HD + 4 pad
#define PS 65       // KTL + 1 pad

__global__ void __launch_bounds__(256, 1) flash_kernel(
    const float* __restrict__ Q, const float* __restrict__ K,
    const float* __restrict__ V, float* __restrict__ O)
{
    extern __shared__ float sm[];
    float* Qs   = sm;                    // QT*PD
    float* Ks   = Qs + QT * PD;          // KTL*PD
    float* Vs   = Ks + KTL * PD;         // KTL*PD
    float* Ss   = Vs + KTL * PD;         // QT*PS
    float* mrow = Ss + QT * PS;          // QT
    float* lrow = mrow + QT;             // QT
    float* cf   = lrow + QT;             // QT

    const int qt = blockIdx.x;
    const int h  = blockIdx.y;
    const int b  = blockIdx.z;
    const int kvh = h >> 2;              // NH/NKV = 4
    const int tid = threadIdx.x;
    const int ty = tid >> 4;
    const int tx = tid & 15;
    const float scale = 0.08838834764831845f;   // 1/sqrt(128)

    // Load Q tile (64 x 128)
    #pragma unroll
    for (int ld = 0; ld < 8; ++ld) {
        int v = tid + (ld << 8);
        int r = v >> 5;
        int c4 = (v & 31) << 2;
        *(float4*)&Qs[r * PD + c4] =
            *(const float4*)&Q[((size_t)(b * NS + qt * QT + r)) * QDIM + h * HD + c4];
    }
    if (tid < QT) { mrow[tid] = -1e30f; lrow[tid] = 0.f; }

    float acc[4][8];
    #pragma unroll
    for (int i = 0; i < 4; ++i)
        #pragma unroll
        for (int j = 0; j < 8; ++j) acc[i][j] = 0.f;

    __syncthreads();

    for (int kt = 0; kt <= qt; ++kt) {
        // Load K,V tiles
        #pragma unroll
        for (int ld = 0; ld < 8; ++ld) {
            int v = tid + (ld << 8);
            int r = v >> 5;
            int c4 = (v & 31) << 2;
            size_t goff = ((size_t)(b * NS + kt * KTL + r)) * KVDIM + kvh * HD + c4;
            *(float4*)&Ks[r * PD + c4] = *(const float4*)&K[goff];
            *(float4*)&Vs[r * PD + c4] = *(const float4*)&V[goff];
        }
        __syncthreads();

        // Scores: 4x4 per thread over d=128
        float s4[4][4];
        #pragma unroll
        for (int i = 0; i < 4; ++i)
            #pragma unroll
            for (int j = 0; j < 4; ++j) s4[i][j] = 0.f;

        #pragma unroll 4
        for (int d = 0; d < HD; d += 4) {
            float4 qa[4], kb[4];
            #pragma unroll
            for (int i = 0; i < 4; ++i) qa[i] = *(const float4*)&Qs[(ty*4 + i) * PD + d];
            #pragma unroll
            for (int j = 0; j < 4; ++j) kb[j] = *(const float4*)&Ks[(tx*4 + j) * PD + d];
            #pragma unroll
            for (int i = 0; i < 4; ++i)
                #pragma unroll
                for (int j = 0; j < 4; ++j) {
                    s4[i][j] = fmaf(qa[i].x, kb[j].x, s4[i][j]);
                    s4[i][j] = fmaf(qa[i].y, kb[j].y, s4[i][j]);
                    s4[i][j] = fmaf(qa[i].z, kb[j].z, s4[i][j]);
                    s4[i][j] = fmaf(qa[i].w, kb[j].w, s4[i][j]);
                }
        }

        // Mask (only diagonal tile has masked entries) + store
        #pragma unroll
        for (int i = 0; i < 4; ++i)
            #pragma unroll
            for (int j = 0; j < 4; ++j) {
                float val = s4[i][j] * scale;
                if (kt == qt && (tx*4 + j) > (ty*4 + i)) val = -1e30f;
                Ss[(ty*4 + i) * PS + tx*4 + j] = val;
            }
        __syncthreads();

        // Online softmax per row (threads 0..63)
        if (tid < QT) {
            const int r = tid;
            float mo = mrow[r];
            float mx = mo;
            #pragma unroll 8
            for (int c = 0; c < KTL; ++c) mx = fmaxf(mx, Ss[r * PS + c]);
            float corr = __expf(mo - mx);
            float sum = 0.f;
            #pragma unroll 8
            for (int c = 0; c < KTL; ++c) {
                float p = __expf(Ss[r * PS + c] - mx);
                Ss[r * PS + c] = p;
                sum += p;
            }
            mrow[r] = mx;
            lrow[r] = lrow[r] * corr + sum;
            cf[r] = corr;
        }
        __syncthreads();

        // Rescale accumulators, then P @ V
        #pragma unroll
        for (int i = 0; i < 4; ++i) {
            float c = cf[ty*4 + i];
            #pragma unroll
            for (int j = 0; j < 8; ++j) acc[i][j] *= c;
        }
        #pragma unroll 4
        for (int k = 0; k < KTL; ++k) {
            float4 v0 = *(const float4*)&Vs[k * PD + tx*8];
            float4 v1 = *(const float4*)&Vs[k * PD + tx*8 + 4];
            #pragma unroll
            for (int i = 0; i < 4; ++i) {
                float p = Ss[(ty*4 + i) * PS + k];
                acc[i][0] = fmaf(p, v0.x, acc[i][0]);
                acc[i][1] = fmaf(p, v0.y, acc[i][1]);
                acc[i][2] = fmaf(p, v0.z, acc[i][2]);
                acc[i][3] = fmaf(p, v0.w, acc[i][3]);
                acc[i][4] = fmaf(p, v1.x, acc[i][4]);
                acc[i][5] = fmaf(p, v1.y, acc[i][5]);
                acc[i][6] = fmaf(p, v1.z, acc[i][6]);
                acc[i][7] = fmaf(p, v1.w, acc[i][7]);
            }
        }
        __syncthreads();   // protect Ks/Vs/Ss before next tile load
    }

    // Epilogue: normalize and write
    #pragma unroll
    for (int i = 0; i < 4; ++i) {
        float inv = 1.0f / lrow[ty*4 + i];
        float* op = O + ((size_t)(b * NS + qt * QT + ty*4 + i)) * QDIM + h * HD + tx*8;
        *(float4*)(op)     = make_float4(acc[i][0]*inv, acc[i][1]*inv, acc[i][2]*inv, acc[i][3]*inv);
        *(float4*)(op + 4) = make_float4(acc[i][4]*inv, acc[i][5]*inv, acc[i][6]*inv, acc[i][7]*inv);
    }
}

// ---------------------------------------------------------------------------
// Launch
// ---------------------------------------------------------------------------
extern "C" void kernel_launch(void* const* d_in, const int* in_sizes, int n_in,
                              void* d_out, int out_size)
{
    const float* hidden = (const float*)d_in[0];
    const float* wq = (const float*)d_in[1];
    const float* wk = (const float*)d_in[2];
    const float* wv = (const float*)d_in[3];
    const float* wo = (const float*)d_in[4];
    float* out = (float*)d_out;

    float *q, *k, *v, *o;
    cudaGetSymbolAddress((void**)&q, g_q);
    cudaGetSymbolAddress((void**)&k, g_k);
    cudaGetSymbolAddress((void**)&v, g_v);
    cudaGetSymbolAddress((void**)&o, g_o);

    // RoPE cos/sin table
    rope_table_kernel<<<(NS * 64 + 255) / 256, 256>>>();

    // QKV projections
    sgemm_nt<<<dim3(QDIM / 128, NM / 128), 256>>>(hidden, wq, q, NM, QDIM, NHID);
    sgemm_nt<<<dim3(KVDIM / 128, NM / 128), 256>>>(hidden, wk, k, NM, KVDIM, NHID);
    sgemm_nt<<<dim3(KVDIM / 128, NM / 128), 256>>>(hidden, wv, v, NM, KVDIM, NHID);

    // RoPE on Q and K (in place)
    rope_apply_kernel<<<(NM * NH * 64) / 256, 256>>>(q, NH);
    rope_apply_kernel<<<(NM * NKV * 64) / 256, 256>>>(k, NKV);

    // Flash attention
    size_t smem = (size_t)(3 * QT * PD + QT * PS + 3 * QT) * sizeof(float);
    cudaFuncSetAttribute(flash_kernel, cudaFuncAttributeMaxDynamicSharedMemorySize, (int)smem);
    flash_kernel<<<dim3(NS / QT, NH, NB), 256, smem>>>(q, k, v, o);

    // Output projection
    sgemm_nt<<<dim3(QDIM / 128, NM / 128), 256>>>(o, wo, out, NM, QDIM, NHID);
}

// round 3
// speedup vs baseline: 1.7958x; 1.7958x over previous
#include <cuda_runtime.h>
#include <math.h>
#include <cstdint>

// Problem constants
#define NB   2
#define NS   2048
#define NHID 4096
#define NH   32
#define NKV  8
#define HD   128
#define NM   (NB*NS)        // 4096
#define QDIM (NH*HD)        // 4096
#define KVDIM (NKV*HD)      // 1024

// Scratch (device globals: allocation-free rule)
__device__ float g_q[(size_t)NM*QDIM];
__device__ float g_k[(size_t)NM*KVDIM];
__device__ float g_v[(size_t)NM*KVDIM];
__device__ float g_o[(size_t)NM*QDIM];
__device__ float g_h [(size_t)NM*NHID];     // tf32-rounded copies
__device__ float g_wq[(size_t)QDIM*NHID];
__device__ float g_wk[(size_t)KVDIM*NHID];
__device__ float g_wv[(size_t)KVDIM*NHID];
__device__ float g_wo[(size_t)NHID*QDIM];
__device__ float g_cos[NS*64];
__device__ float g_sin[NS*64];

// ---------------------------------------------------------------------------
// helpers
// ---------------------------------------------------------------------------
__device__ __forceinline__ uint32_t smem_to_u32(const void* p) {
    uint32_t a;
    asm("{ .reg .u64 t; cvta.to.shared.u64 t, %1; cvt.u32.u64 %0, t; }" : "=r"(a) : "l"(p));
    return a;
}
__device__ __forceinline__ void cp_async16(uint32_t dst, const void* src) {
    asm volatile("cp.async.cg.shared.global [%0], [%1], 16;" :: "r"(dst), "l"(src) : "memory");
}
__device__ __forceinline__ void mma_tf32(float& d0, float& d1, float& d2, float& d3,
                                         uint32_t a0, uint32_t a1, uint32_t a2, uint32_t a3,
                                         uint32_t b0, uint32_t b1) {
    asm volatile("mma.sync.aligned.m16n8k8.row.col.f32.tf32.tf32.f32 "
        "{%0,%1,%2,%3}, {%4,%5,%6,%7}, {%8,%9}, {%0,%1,%2,%3};"
        : "+f"(d0), "+f"(d1), "+f"(d2), "+f"(d3)
        : "r"(a0), "r"(a1), "r"(a2), "r"(a3), "r"(b0), "r"(b1));
}

// ---------------------------------------------------------------------------
// tf32 RNA pre-rounding (mma.sync tf32 truncates; RNA pre-round unbiases)
// ---------------------------------------------------------------------------
__global__ void round_tf32_kernel(const float4* __restrict__ in, float4* __restrict__ out, int n4)
{
    int i = blockIdx.x * blockDim.x + threadIdx.x;
    if (i >= n4) return;
    float4 v = in[i];
    uint32_t a, b, c, d;
    asm("cvt.rna.tf32.f32 %0, %1;" : "=r"(a) : "f"(v.x));
    asm("cvt.rna.tf32.f32 %0, %1;" : "=r"(b) : "f"(v.y));
    asm("cvt.rna.tf32.f32 %0, %1;" : "=r"(c) : "f"(v.z));
    asm("cvt.rna.tf32.f32 %0, %1;" : "=r"(d) : "f"(v.w));
    out[i] = make_float4(__uint_as_float(a), __uint_as_float(b),
                         __uint_as_float(c), __uint_as_float(d));
}

// ---------------------------------------------------------------------------
// tf32 mma.sync NT GEMM: C[M,N] = A[M,K] * B[N,K]^T (row-major).
// 128x128x32 CTA tile, 256 threads (2x4 warps, 64x32 warp tile),
// 3-stage cp.async pipeline, smem rows padded to 36 floats (conflict-free).
// ---------------------------------------------------------------------------
#define BK       32
#define ROWPAD   36                       // floats per smem row
#define TILE_F   (128*ROWPAD)             // 4608 floats per operand tile
#define STAGE_F  (2*TILE_F)               // A then B
#define GEMM_SMEM (3*STAGE_F*4)           // 110592 bytes

__global__ void __launch_bounds__(256) gemm_tf32(
    const float* __restrict__ A, const float* __restrict__ B, float* __restrict__ C,
    int N, int K)
{
    extern __shared__ float sm[];
    const uint32_t smem_u32 = smem_to_u32(sm);

    const int tid  = threadIdx.x;
    const int wid  = tid >> 5;
    const int lane = tid & 31;
    const int wm   = (wid >> 2) * 64;     // warp m offset in CTA tile
    const int wn   = (wid & 3) * 32;      // warp n offset
    const int gid  = lane >> 2;           // 0..7
    const int tig  = lane & 3;            // 0..3
    const int bm = blockIdx.y << 7;
    const int bn = blockIdx.x << 7;
    const int NK = K >> 5;                // BK=32 chunks

    const float* Ab = A + (size_t)bm * K;
    const float* Bb = B + (size_t)bn * K;

    float acc[4][4][4];                   // [mt][nt][frag]
    #pragma unroll
    for (int i = 0; i < 4; ++i)
        #pragma unroll
        for (int j = 0; j < 4; ++j)
            #pragma unroll
            for (int r = 0; r < 4; ++r) acc[i][j][r] = 0.f;

    // async tile load: 128 rows x 8 16B-chunks per operand, 4+4 per thread
    auto load_st = [&](int iter, int s) {
        const int kof = iter << 5;
        const uint32_t sa = smem_u32 + (uint32_t)(s * STAGE_F) * 4;
        const uint32_t sb = sa + TILE_F * 4;
        #pragma unroll
        for (int j = 0; j < 4; ++j) {
            int v  = tid + (j << 8);
            int rr = v >> 3;
            int c4 = v & 7;                               // 16B chunk in row
            uint32_t so = (uint32_t)(rr * ROWPAD + c4 * 4) * 4;
            cp_async16(sa + so, Ab + (size_t)rr * K + kof + c4 * 4);
            cp_async16(sb + so, Bb + (size_t)rr * K + kof + c4 * 4);
        }
    };

    load_st(0, 0); asm volatile("cp.async.commit_group;" ::: "memory");
    load_st(1, 1); asm volatile("cp.async.commit_group;" ::: "memory");

    for (int i = 0; i < NK; ++i) {
        asm volatile("cp.async.wait_group 1;" ::: "memory");
        __syncthreads();

        if (i + 2 < NK) load_st(i + 2, (i + 2) % 3);
        asm volatile("cp.async.commit_group;" ::: "memory");   // one group per iter

        const int s = i % 3;
        const uint32_t* Au = (const uint32_t*)(sm + s * STAGE_F) + (wm + gid) * ROWPAD + tig;
        const uint32_t* Bu = (const uint32_t*)(sm + s * STAGE_F + TILE_F) + (wn + gid) * ROWPAD + tig;

        #pragma unroll
        for (int ks = 0; ks < 4; ++ks) {
            const int k0 = ks << 3;
            uint32_t af[4][4], bf[4][2];
            #pragma unroll
            for (int mt = 0; mt < 4; ++mt) {
                const uint32_t* p = Au + mt * (16 * ROWPAD) + k0;
                af[mt][0] = p[0];
                af[mt][1] = p[8 * ROWPAD];
                af[mt][2] = p[4];
                af[mt][3] = p[8 * ROWPAD + 4];
            }
            #pragma unroll
            for (int nt = 0; nt < 4; ++nt) {
                const uint32_t* p = Bu + nt * (8 * ROWPAD) + k0;
                bf[nt][0] = p[0];
                bf[nt][1] = p[4];
            }
            #pragma unroll
            for (int mt = 0; mt < 4; ++mt)
                #pragma unroll
                for (int nt = 0; nt < 4; ++nt)
                    mma_tf32(acc[mt][nt][0], acc[mt][nt][1], acc[mt][nt][2], acc[mt][nt][3],
                             af[mt][0], af[mt][1], af[mt][2], af[mt][3],
                             bf[nt][0], bf[nt][1]);
        }
    }

    // Epilogue: mma frag layout -> C
    #pragma unroll
    for (int mt = 0; mt < 4; ++mt) {
        int r0 = bm + wm + mt * 16 + gid;
        #pragma unroll
        for (int nt = 0; nt < 4; ++nt) {
            int c0 = bn + wn + nt * 8 + 2 * tig;
            *(float2*)(C + (size_t)r0 * N + c0)       = make_float2(acc[mt][nt][0], acc[mt][nt][1]);
            *(float2*)(C + (size_t)(r0 + 8) * N + c0) = make_float2(acc[mt][nt][2], acc[mt][nt][3]);
        }
    }
}

// ---------------------------------------------------------------------------
// RoPE
// ---------------------------------------------------------------------------
__global__ void rope_table_kernel()
{
    int idx = blockIdx.x * blockDim.x + threadIdx.x;
    if (idx >= NS * 64) return;
    int pos = idx >> 6;
    int i = idx & 63;
    float inv = 1.0f / powf(10000.0f, (float)i / 64.0f);
    float f = (float)pos * inv;
    g_cos[idx] = cosf(f);
    g_sin[idx] = sinf(f);
}

__global__ void rope_apply_kernel(float* __restrict__ X, int nheads)
{
    int idx = blockIdx.x * blockDim.x + threadIdx.x;
    int total = NM * nheads * 64;
    if (idx >= total) return;
    int i = idx & 63;
    int h = (idx >> 6) % nheads;
    int m = idx / (nheads * 64);
    int pos = m & (NS - 1);
    float* p = X + (size_t)m * nheads * HD + h * HD + i;
    float x1 = p[0], x2 = p[64];
    float c = g_cos[pos * 64 + i];
    float sn = g_sin[pos * 64 + i];
    p[0]  = x1 * c - x2 * sn;
    p[64] = x1 * sn + x2 * c;
}

// ---------------------------------------------------------------------------
// Flash attention (fp32 SIMT — unchanged; mma.sync port is next round)
// ---------------------------------------------------------------------------
#define QT 64
#define KTL 64
#define PD 132
#define PS 65

__global__ void __launch_bounds__(256, 1) flash_kernel(
    const float* __restrict__ Q, const float* __restrict__ K,
    const float* __restrict__ V, float* __restrict__ O)
{
    extern __shared__ float smf[];
    float* Qs   = smf;
    float* Ks   = Qs + QT * PD;
    float* Vs   = Ks + KTL * PD;
    float* Ss   = Vs + KTL * PD;
    float* mrow = Ss + QT * PS;
    float* lrow = mrow + QT;
    float* cf   = lrow + QT;

    const int qt = blockIdx.x;
    const int h  = blockIdx.y;
    const int b  = blockIdx.z;
    const int kvh = h >> 2;
    const int tid = threadIdx.x;
    const int ty = tid >> 4;
    const int tx = tid & 15;
    const float scale = 0.08838834764831845f;

    #pragma unroll
    for (int ld = 0; ld < 8; ++ld) {
        int v = tid + (ld << 8);
        int r = v >> 5;
        int c4 = (v & 31) << 2;
        *(float4*)&Qs[r * PD + c4] =
            *(const float4*)&Q[((size_t)(b * NS + qt * QT + r)) * QDIM + h * HD + c4];
    }
    if (tid < QT) { mrow[tid] = -1e30f; lrow[tid] = 0.f; }

    float acc[4][8];
    #pragma unroll
    for (int i = 0; i < 4; ++i)
        #pragma unroll
        for (int j = 0; j < 8; ++j) acc[i][j] = 0.f;

    __syncthreads();

    for (int kt = 0; kt <= qt; ++kt) {
        #pragma unroll
        for (int ld = 0; ld < 8; ++ld) {
            int v = tid + (ld << 8);
            int r = v >> 5;
            int c4 = (v & 31) << 2;
            size_t goff = ((size_t)(b * NS + kt * KTL + r)) * KVDIM + kvh * HD + c4;
            *(float4*)&Ks[r * PD + c4] = *(const float4*)&K[goff];
            *(float4*)&Vs[r * PD + c4] = *(const float4*)&V[goff];
        }
        __syncthreads();

        float s4[4][4];
        #pragma unroll
        for (int i = 0; i < 4; ++i)
            #pragma unroll
            for (int j = 0; j < 4; ++j) s4[i][j] = 0.f;

        #pragma unroll 4
        for (int d = 0; d < HD; d += 4) {
            float4 qa[4], kb[4];
            #pragma unroll
            for (int i = 0; i < 4; ++i) qa[i] = *(const float4*)&Qs[(ty*4 + i) * PD + d];
            #pragma unroll
            for (int j = 0; j < 4; ++j) kb[j] = *(const float4*)&Ks[(tx*4 + j) * PD + d];
            #pragma unroll
            for (int i = 0; i < 4; ++i)
                #pragma unroll
                for (int j = 0; j < 4; ++j) {
                    s4[i][j] = fmaf(qa[i].x, kb[j].x, s4[i][j]);
                    s4[i][j] = fmaf(qa[i].y, kb[j].y, s4[i][j]);
                    s4[i][j] = fmaf(qa[i].z, kb[j].z, s4[i][j]);
                    s4[i][j] = fmaf(qa[i].w, kb[j].w, s4[i][j]);
                }
        }

        #pragma unroll
        for (int i = 0; i < 4; ++i)
            #pragma unroll
            for (int j = 0; j < 4; ++j) {
                float val = s4[i][j] * scale;
                if (kt == qt && (tx*4 + j) > (ty*4 + i)) val = -1e30f;
                Ss[(ty*4 + i) * PS + tx*4 + j] = val;
            }
        __syncthreads();

        if (tid < QT) {
            const int r = tid;
            float mo = mrow[r];
            float mx = mo;
            #pragma unroll 8
            for (int c = 0; c < KTL; ++c) mx = fmaxf(mx, Ss[r * PS + c]);
            float corr = __expf(mo - mx);
            float sum = 0.f;
            #pragma unroll 8
            for (int c = 0; c < KTL; ++c) {
                float p = __expf(Ss[r * PS + c] - mx);
                Ss[r * PS + c] = p;
                sum += p;
            }
            mrow[r] = mx;
            lrow[r] = lrow[r] * corr + sum;
            cf[r] = corr;
        }
        __syncthreads();

        #pragma unroll
        for (int i = 0; i < 4; ++i) {
            float c = cf[ty*4 + i];
            #pragma unroll
            for (int j = 0; j < 8; ++j) acc[i][j] *= c;
        }
        #pragma unroll 4
        for (int k = 0; k < KTL; ++k) {
            float4 v0 = *(const float4*)&Vs[k * PD + tx*8];
            float4 v1 = *(const float4*)&Vs[k * PD + tx*8 + 4];
            #pragma unroll
            for (int i = 0; i < 4; ++i) {
                float p = Ss[(ty*4 + i) * PS + k];
                acc[i][0] = fmaf(p, v0.x, acc[i][0]);
                acc[i][1] = fmaf(p, v0.y, acc[i][1]);
                acc[i][2] = fmaf(p, v0.z, acc[i][2]);
                acc[i][3] = fmaf(p, v0.w, acc[i][3]);
                acc[i][4] = fmaf(p, v1.x, acc[i][4]);
                acc[i][5] = fmaf(p, v1.y, acc[i][5]);
                acc[i][6] = fmaf(p, v1.z, acc[i][6]);
                acc[i][7] = fmaf(p, v1.w, acc[i][7]);
            }
        }
        __syncthreads();
    }

    #pragma unroll
    for (int i = 0; i < 4; ++i) {
        float inv = 1.0f / lrow[ty*4 + i];
        float* op = O + ((size_t)(b * NS + qt * QT + ty*4 + i)) * QDIM + h * HD + tx*8;
        *(float4*)(op)     = make_float4(acc[i][0]*inv, acc[i][1]*inv, acc[i][2]*inv, acc[i][3]*inv);
        *(float4*)(op + 4) = make_float4(acc[i][4]*inv, acc[i][5]*inv, acc[i][6]*inv, acc[i][7]*inv);
    }
}

// ---------------------------------------------------------------------------
// Launch
// ---------------------------------------------------------------------------
extern "C" void kernel_launch(void* const* d_in, const int* in_sizes, int n_in,
                              void* d_out, int out_size)
{
    const float* hidden = (const float*)d_in[0];
    const float* wq = (const float*)d_in[1];
    const float* wk = (const float*)d_in[2];
    const float* wv = (const float*)d_in[3];
    const float* wo = (const float*)d_in[4];
    float* out = (float*)d_out;

    float *q, *k, *v, *o, *h2, *wq2, *wk2, *wv2, *wo2;
    cudaGetSymbolAddress((void**)&q,  g_q);
    cudaGetSymbolAddress((void**)&k,  g_k);
    cudaGetSymbolAddress((void**)&v,  g_v);
    cudaGetSymbolAddress((void**)&o,  g_o);
    cudaGetSymbolAddress((void**)&h2, g_h);
    cudaGetSymbolAddress((void**)&wq2, g_wq);
    cudaGetSymbolAddress((void**)&wk2, g_wk);
    cudaGetSymbolAddress((void**)&wv2, g_wv);
    cudaGetSymbolAddress((void**)&wo2, g_wo);

    cudaFuncSetAttribute(gemm_tf32, cudaFuncAttributeMaxDynamicSharedMemorySize, GEMM_SMEM);

    // tf32-RNA pre-rounding of all GEMM operands
    {
        int n4;
        n4 = NM*NHID/4;    round_tf32_kernel<<<(n4+255)/256, 256>>>((const float4*)hidden, (float4*)h2,  n4);
        n4 = QDIM*NHID/4;  round_tf32_kernel<<<(n4+255)/256, 256>>>((const float4*)wq,     (float4*)wq2, n4);
        n4 = KVDIM*NHID/4; round_tf32_kernel<<<(n4+255)/256, 256>>>((const float4*)wk,     (float4*)wk2, n4);
        n4 = KVDIM*NHID/4; round_tf32_kernel<<<(n4+255)/256, 256>>>((const float4*)wv,     (float4*)wv2, n4);
        n4 = NHID*QDIM/4;  round_tf32_kernel<<<(n4+255)/256, 256>>>((const float4*)wo,     (float4*)wo2, n4);
    }

    rope_table_kernel<<<(NS * 64 + 255) / 256, 256>>>();

    // Projections on tf32 mma.sync
    gemm_tf32<<<dim3(QDIM/128,  NM/128), 256, GEMM_SMEM>>>(h2, wq2, q, QDIM,  NHID);
    gemm_tf32<<<dim3(KVDIM/128, NM/128), 256, GEMM_SMEM>>>(h2, wk2, k, KVDIM, NHID);
    gemm_tf32<<<dim3(KVDIM/128, NM/128), 256, GEMM_SMEM>>>(h2, wv2, v, KVDIM, NHID);

    rope_apply_kernel<<<(NM * NH  * 64) / 256, 256>>>(q, NH);
    rope_apply_kernel<<<(NM * NKV * 64) / 256, 256>>>(k, NKV);

    size_t smem = (size_t)(3 * QT * PD + QT * PS + 3 * QT) * sizeof(float);
    cudaFuncSetAttribute(flash_kernel, cudaFuncAttributeMaxDynamicSharedMemorySize, (int)smem);
    flash_kernel<<<dim3(NS / QT, NH, NB), 256, smem>>>(q, k, v, o);

    // Round attention output in-place, then O projection
    {
        int n4 = NM*QDIM/4;
        round_tf32_kernel<<<(n4+255)/256, 256>>>((const float4*)o, (float4*)o, n4);
    }
    gemm_tf32<<<dim3(QDIM/128, NM/128), 256, GEMM_SMEM>>>(o, wo2, out, QDIM, NHID);
}

// round 4
// speedup vs baseline: 2.9605x; 1.6486x over previous
#include <cuda_runtime.h>
#include <math.h>
#include <cstdint>

// Problem constants
#define NB   2
#define NS   2048
#define NHID 4096
#define NH   32
#define NKV  8
#define HD   128
#define NM   (NB*NS)        // 4096
#define QDIM (NH*HD)        // 4096
#define KVDIM (NKV*HD)      // 1024

// Scratch (device globals: allocation-free rule)
__device__ float g_q[(size_t)NM*QDIM];
__device__ float g_k[(size_t)NM*KVDIM];
__device__ float g_v[(size_t)NM*KVDIM];
__device__ float g_o[(size_t)NM*QDIM];
__device__ float g_h [(size_t)NM*NHID];
__device__ float g_wq[(size_t)QDIM*NHID];
__device__ float g_wk[(size_t)KVDIM*NHID];
__device__ float g_wv[(size_t)KVDIM*NHID];
__device__ float g_wo[(size_t)NHID*QDIM];
__device__ float g_qhi[(size_t)NM*QDIM];
__device__ float g_qlo[(size_t)NM*QDIM];
__device__ float g_khi[(size_t)NM*KVDIM];
__device__ float g_klo[(size_t)NM*KVDIM];
__device__ float g_cos[NS*64];
__device__ float g_sin[NS*64];

// ---------------------------------------------------------------------------
// helpers
// ---------------------------------------------------------------------------
__device__ __forceinline__ uint32_t smem_to_u32(const void* p) {
    uint32_t a;
    asm("{ .reg .u64 t; cvta.to.shared.u64 t, %1; cvt.u32.u64 %0, t; }" : "=r"(a) : "l"(p));
    return a;
}
__device__ __forceinline__ void cp_async16(uint32_t dst, const void* src) {
    asm volatile("cp.async.cg.shared.global [%0], [%1], 16;" :: "r"(dst), "l"(src) : "memory");
}
__device__ __forceinline__ void mma_tf32(float& d0, float& d1, float& d2, float& d3,
                                         uint32_t a0, uint32_t a1, uint32_t a2, uint32_t a3,
                                         uint32_t b0, uint32_t b1) {
    asm volatile("mma.sync.aligned.m16n8k8.row.col.f32.tf32.tf32.f32 "
        "{%0,%1,%2,%3}, {%4,%5,%6,%7}, {%8,%9}, {%0,%1,%2,%3};"
        : "+f"(d0), "+f"(d1), "+f"(d2), "+f"(d3)
        : "r"(a0), "r"(a1), "r"(a2), "r"(a3), "r"(b0), "r"(b1));
}
__device__ __forceinline__ float rna_tf32(float x) {
    uint32_t u;
    asm("cvt.rna.tf32.f32 %0, %1;" : "=r"(u) : "f"(x));
    return __uint_as_float(u);
}

// ---------------------------------------------------------------------------
// elementwise: tf32 RNA rounding / hi-lo split
// ---------------------------------------------------------------------------
__global__ void round_tf32_kernel(const float4* __restrict__ in, float4* __restrict__ out, int n4)
{
    int i = blockIdx.x * blockDim.x + threadIdx.x;
    if (i >= n4) return;
    float4 v = in[i];
    out[i] = make_float4(rna_tf32(v.x), rna_tf32(v.y), rna_tf32(v.z), rna_tf32(v.w));
}

__global__ void split_tf32_kernel(const float4* __restrict__ in,
                                  float4* __restrict__ hi, float4* __restrict__ lo, int n4)
{
    int i = blockIdx.x * blockDim.x + threadIdx.x;
    if (i >= n4) return;
    float4 v = in[i];
    float hx = rna_tf32(v.x), hy = rna_tf32(v.y), hz = rna_tf32(v.z), hw = rna_tf32(v.w);
    hi[i] = make_float4(hx, hy, hz, hw);
    lo[i] = make_float4(rna_tf32(v.x - hx), rna_tf32(v.y - hy),
                        rna_tf32(v.z - hz), rna_tf32(v.w - hw));
}

// ---------------------------------------------------------------------------
// tf32 mma.sync NT GEMM (unchanged from Round 3 — validated)
// ---------------------------------------------------------------------------
#define ROWPAD   36
#define TILE_F   (128*ROWPAD)
#define STAGE_F  (2*TILE_F)
#define GEMM_SMEM (3*STAGE_F*4)

__global__ void __launch_bounds__(256) gemm_tf32(
    const float* __restrict__ A, const float* __restrict__ B, float* __restrict__ C,
    int N, int K)
{
    extern __shared__ float sm[];
    const uint32_t smem_u32 = smem_to_u32(sm);

    const int tid  = threadIdx.x;
    const int wid  = tid >> 5;
    const int lane = tid & 31;
    const int wm   = (wid >> 2) * 64;
    const int wn   = (wid & 3) * 32;
    const int gid  = lane >> 2;
    const int tig  = lane & 3;
    const int bm = blockIdx.y << 7;
    const int bn = blockIdx.x << 7;
    const int NK = K >> 5;

    const float* Ab = A + (size_t)bm * K;
    const float* Bb = B + (size_t)bn * K;

    float acc[4][4][4];
    #pragma unroll
    for (int i = 0; i < 4; ++i)
        #pragma unroll
        for (int j = 0; j < 4; ++j)
            #pragma unroll
            for (int r = 0; r < 4; ++r) acc[i][j][r] = 0.f;

    auto load_st = [&](int iter, int s) {
        const int kof = iter << 5;
        const uint32_t sa = smem_u32 + (uint32_t)(s * STAGE_F) * 4;
        const uint32_t sb = sa + TILE_F * 4;
        #pragma unroll
        for (int j = 0; j < 4; ++j) {
            int v  = tid + (j << 8);
            int rr = v >> 3;
            int c4 = v & 7;
            uint32_t so = (uint32_t)(rr * ROWPAD + c4 * 4) * 4;
            cp_async16(sa + so, Ab + (size_t)rr * K + kof + c4 * 4);
            cp_async16(sb + so, Bb + (size_t)rr * K + kof + c4 * 4);
        }
    };

    load_st(0, 0); asm volatile("cp.async.commit_group;" ::: "memory");
    load_st(1, 1); asm volatile("cp.async.commit_group;" ::: "memory");

    for (int i = 0; i < NK; ++i) {
        asm volatile("cp.async.wait_group 1;" ::: "memory");
        __syncthreads();

        if (i + 2 < NK) load_st(i + 2, (i + 2) % 3);
        asm volatile("cp.async.commit_group;" ::: "memory");

        const int s = i % 3;
        const uint32_t* Au = (const uint32_t*)(sm + s * STAGE_F) + (wm + gid) * ROWPAD + tig;
        const uint32_t* Bu = (const uint32_t*)(sm + s * STAGE_F + TILE_F) + (wn + gid) * ROWPAD + tig;

        #pragma unroll
        for (int ks = 0; ks < 4; ++ks) {
            const int k0 = ks << 3;
            uint32_t af[4][4], bf[4][2];
            #pragma unroll
            for (int mt = 0; mt < 4; ++mt) {
                const uint32_t* p = Au + mt * (16 * ROWPAD) + k0;
                af[mt][0] = p[0];
                af[mt][1] = p[8 * ROWPAD];
                af[mt][2] = p[4];
                af[mt][3] = p[8 * ROWPAD + 4];
            }
            #pragma unroll
            for (int nt = 0; nt < 4; ++nt) {
                const uint32_t* p = Bu + nt * (8 * ROWPAD) + k0;
                bf[nt][0] = p[0];
                bf[nt][1] = p[4];
            }
            #pragma unroll
            for (int mt = 0; mt < 4; ++mt)
                #pragma unroll
                for (int nt = 0; nt < 4; ++nt)
                    mma_tf32(acc[mt][nt][0], acc[mt][nt][1], acc[mt][nt][2], acc[mt][nt][3],
                             af[mt][0], af[mt][1], af[mt][2], af[mt][3],
                             bf[nt][0], bf[nt][1]);
        }
    }

    #pragma unroll
    for (int mt = 0; mt < 4; ++mt) {
        int r0 = bm + wm + mt * 16 + gid;
        #pragma unroll
        for (int nt = 0; nt < 4; ++nt) {
            int c0 = bn + wn + nt * 8 + 2 * tig;
            *(float2*)(C + (size_t)r0 * N + c0)       = make_float2(acc[mt][nt][0], acc[mt][nt][1]);
            *(float2*)(C + (size_t)(r0 + 8) * N + c0) = make_float2(acc[mt][nt][2], acc[mt][nt][3]);
        }
    }
}

// ---------------------------------------------------------------------------
// RoPE
// ---------------------------------------------------------------------------
__global__ void rope_table_kernel()
{
    int idx = blockIdx.x * blockDim.x + threadIdx.x;
    if (idx >= NS * 64) return;
    int pos = idx >> 6;
    int i = idx & 63;
    float inv = 1.0f / powf(10000.0f, (float)i / 64.0f);
    float f = (float)pos * inv;
    g_cos[idx] = cosf(f);
    g_sin[idx] = sinf(f);
}

__global__ void rope_apply_kernel(float* __restrict__ X, int nheads)
{
    int idx = blockIdx.x * blockDim.x + threadIdx.x;
    int total = NM * nheads * 64;
    if (idx >= total) return;
    int i = idx & 63;
    int h = (idx >> 6) % nheads;
    int m = idx / (nheads * 64);
    int pos = m & (NS - 1);
    float* p = X + (size_t)m * nheads * HD + h * HD + i;
    float x1 = p[0], x2 = p[64];
    float c = g_cos[pos * 64 + i];
    float sn = g_sin[pos * 64 + i];
    p[0]  = x1 * c - x2 * sn;
    p[64] = x1 * sn + x2 * c;
}

// ---------------------------------------------------------------------------
// Flash attention on mma.sync tf32.
// CTA = 64 q-rows x (k in 32-chunks). 256 threads / 8 warps.
// QK^T: 3xTF32 split (fp32-accurate scores). PV: plain tf32.
// smem: Qhi/Qlo 64x128(pad132), 2-stage {Khi,Klo,V} 32x132, S 64x36, m/l/cf.
// ---------------------------------------------------------------------------
#define FQT 64
#define FKT 32
#define QP  132
#define SP  36
#define KVSTAGE (3*FKT*QP)                 // floats per K/V stage
#define FLASH_SMEM ((2*FQT*QP + 2*KVSTAGE + FQT*SP + 3*FQT)*4)

__global__ void __launch_bounds__(256, 1) flash_mma(
    const float* __restrict__ Qhg, const float* __restrict__ Qlg,
    const float* __restrict__ Khg, const float* __restrict__ Klg,
    const float* __restrict__ Vg, float* __restrict__ O)
{
    extern __shared__ float sm[];
    float* sQh = sm;
    float* sQl = sm + FQT*QP;
    float* sKV = sm + 2*FQT*QP;
    float* sS  = sm + 2*FQT*QP + 2*KVSTAGE;
    float* sM  = sS + FQT*SP;
    float* sL  = sM + FQT;
    float* sC  = sL + FQT;

    const int qt = blockIdx.x, h = blockIdx.y, b = blockIdx.z;
    const int kvh = h >> 2;
    const int tid = threadIdx.x;
    const int w = tid >> 5, lane = tid & 31;
    const int gid = lane >> 2, tig = lane & 3;
    const int wm = (w & 3) * 16;          // m offset (QK and PV)
    const int wn = (w >> 2) * 16;         // QK n offset
    const int pn = (w >> 2) * 64;         // PV n offset
    const uint32_t su = smem_to_u32(sm);
    const float scale = 0.08838834764831845f;

    // ---- preload Q(hi,lo) + stage0 K/V ----
    {
        const size_t qoff = ((size_t)(b*NS + qt*FQT))*QDIM + h*HD;
        #pragma unroll
        for (int j = 0; j < 8; ++j) {
            int vv = tid + (j << 8);           // 0..2047
            int r = vv >> 5, c = (vv & 31) << 2;
            uint32_t d = su + (uint32_t)(r*QP + c)*4;
            const size_t g = qoff + (size_t)r*QDIM + c;
            cp_async16(d,                Qhg + g);
            cp_async16(d + FQT*QP*4,     Qlg + g);
        }
    }
    auto load_kv = [&](int kt, int s) {
        const size_t koff = ((size_t)(b*NS + kt*FKT))*KVDIM + kvh*HD;
        const uint32_t du = su + (uint32_t)(2*FQT*QP + s*KVSTAGE)*4;
        #pragma unroll
        for (int j = 0; j < 4; ++j) {
            int vv = tid + (j << 8);           // 0..1023
            int r = vv >> 5, c = (vv & 31) << 2;
            const size_t g = koff + (size_t)r*KVDIM + c;
            uint32_t d = du + (uint32_t)(r*QP + c)*4;
            cp_async16(d,                Khg + g);
            cp_async16(d + FKT*QP*4,     Klg + g);
            cp_async16(d + 2*FKT*QP*4,   Vg  + g);
        }
    };
    load_kv(0, 0);
    asm volatile("cp.async.commit_group;" ::: "memory");

    if (tid < FQT) { sM[tid] = -1e30f; sL[tid] = 0.f; }

    float acc[8][4];
    #pragma unroll
    for (int i = 0; i < 8; ++i)
        #pragma unroll
        for (int j = 0; j < 4; ++j) acc[i][j] = 0.f;

    const int nkt = 2*qt + 2;
    int buf = 0;
    for (int kt = 0; kt < nkt; ++kt) {
        if (kt + 1 < nkt) load_kv(kt + 1, buf ^ 1);
        asm volatile("cp.async.commit_group;" ::: "memory");
        asm volatile("cp.async.wait_group 1;" ::: "memory");
        __syncthreads();

        // ---- QK^T (3xTF32 split) ----
        const float* Khs = sKV + buf*KVSTAGE;
        const float* Kls = Khs + FKT*QP;
        {
            float s0[4] = {0,0,0,0}, s1[4] = {0,0,0,0};
            const float* qh  = sQh + (wm+gid)*QP + tig;
            const float* ql  = sQl + (wm+gid)*QP + tig;
            const float* kh0 = Khs + (wn+gid)*QP + tig;
            const float* kh1 = Khs + (wn+8+gid)*QP + tig;
            const float* kl0 = Kls + (wn+gid)*QP + tig;
            const float* kl1 = Kls + (wn+8+gid)*QP + tig;
            #pragma unroll
            for (int ks = 0; ks < 16; ++ks) {
                const int k0 = ks << 3;
                uint32_t ah0 = __float_as_uint(qh[k0]);
                uint32_t ah1 = __float_as_uint(qh[k0 + 8*QP]);
                uint32_t ah2 = __float_as_uint(qh[k0 + 4]);
                uint32_t ah3 = __float_as_uint(qh[k0 + 8*QP + 4]);
                uint32_t al0 = __float_as_uint(ql[k0]);
                uint32_t al1 = __float_as_uint(ql[k0 + 8*QP]);
                uint32_t al2 = __float_as_uint(ql[k0 + 4]);
                uint32_t al3 = __float_as_uint(ql[k0 + 8*QP + 4]);
                uint32_t bh00 = __float_as_uint(kh0[k0]), bh01 = __float_as_uint(kh0[k0+4]);
                uint32_t bh10 = __float_as_uint(kh1[k0]), bh11 = __float_as_uint(kh1[k0+4]);
                uint32_t bl00 = __float_as_uint(kl0[k0]), bl01 = __float_as_uint(kl0[k0+4]);
                uint32_t bl10 = __float_as_uint(kl1[k0]), bl11 = __float_as_uint(kl1[k0+4]);
                mma_tf32(s0[0],s0[1],s0[2],s0[3], ah0,ah1,ah2,ah3, bh00,bh01);
                mma_tf32(s0[0],s0[1],s0[2],s0[3], ah0,ah1,ah2,ah3, bl00,bl01);
                mma_tf32(s0[0],s0[1],s0[2],s0[3], al0,al1,al2,al3, bh00,bh01);
                mma_tf32(s1[0],s1[1],s1[2],s1[3], ah0,ah1,ah2,ah3, bh10,bh11);
                mma_tf32(s1[0],s1[1],s1[2],s1[3], ah0,ah1,ah2,ah3, bl10,bl11);
                mma_tf32(s1[0],s1[1],s1[2],s1[3], al0,al1,al2,al3, bh10,bh11);
            }
            *(float2*)&sS[(wm+gid)*SP   + wn     + 2*tig] = make_float2(s0[0], s0[1]);
            *(float2*)&sS[(wm+gid+8)*SP + wn     + 2*tig] = make_float2(s0[2], s0[3]);
            *(float2*)&sS[(wm+gid)*SP   + wn + 8 + 2*tig] = make_float2(s1[0], s1[1]);
            *(float2*)&sS[(wm+gid+8)*SP + wn + 8 + 2*tig] = make_float2(s1[2], s1[3]);
        }
        __syncthreads();

        // ---- online softmax: 4 threads per row, 8 cols each ----
        {
            const int r = tid >> 2, t = tid & 3;
            float* srow = &sS[r*SP + t*8];
            float4 u0 = *(float4*)srow;
            float4 u1 = *(float4*)(srow + 4);
            float vals[8] = {u0.x,u0.y,u0.z,u0.w,u1.x,u1.y,u1.z,u1.w};
            const int rq = qt*FQT + r;
            const int ck0 = kt*FKT + t*8;
            #pragma unroll
            for (int i = 0; i < 8; ++i)
                vals[i] = (ck0 + i <= rq) ? vals[i]*scale : -1e30f;
            float mx = vals[0];
            #pragma unroll
            for (int i = 1; i < 8; ++i) mx = fmaxf(mx, vals[i]);
            mx = fmaxf(mx, __shfl_xor_sync(0xffffffffu, mx, 1));
            mx = fmaxf(mx, __shfl_xor_sync(0xffffffffu, mx, 2));
            const float mo = sM[r];
            const float nm = fmaxf(mo, mx);
            float sum = 0.f;
            #pragma unroll
            for (int i = 0; i < 8; ++i) { vals[i] = __expf(vals[i] - nm); sum += vals[i]; }
            sum += __shfl_xor_sync(0xffffffffu, sum, 1);
            sum += __shfl_xor_sync(0xffffffffu, sum, 2);
            if (t == 0) {
                const float corr = __expf(mo - nm);
                sM[r] = nm;
                sL[r] = sL[r]*corr + sum;
                sC[r] = corr;
            }
            #pragma unroll
            for (int i = 0; i < 8; ++i) vals[i] = rna_tf32(vals[i]);
            *(float4*)srow       = make_float4(vals[0], vals[1], vals[2], vals[3]);
            *(float4*)(srow + 4) = make_float4(vals[4], vals[5], vals[6], vals[7]);
        }
        __syncthreads();

        // ---- PV (plain tf32), acc persistent in registers ----
        {
            const float* Vs = sKV + buf*KVSTAGE + 2*FKT*QP;
            const float cc0 = sC[wm+gid], cc1 = sC[wm+gid+8];
            #pragma unroll
            for (int nt = 0; nt < 8; ++nt) {
                acc[nt][0] *= cc0; acc[nt][1] *= cc0;
                acc[nt][2] *= cc1; acc[nt][3] *= cc1;
            }
            const float* pp = sS + (wm+gid)*SP + tig;
            #pragma unroll
            for (int ks = 0; ks < 4; ++ks) {
                const int k0 = ks << 3;
                uint32_t a0 = __float_as_uint(pp[k0]);
                uint32_t a1 = __float_as_uint(pp[k0 + 8*SP]);
                uint32_t a2 = __float_as_uint(pp[k0 + 4]);
                uint32_t a3 = __float_as_uint(pp[k0 + 8*SP + 4]);
                const float* vb = Vs + (k0 + tig)*QP + pn + gid;
                #pragma unroll
                for (int nt = 0; nt < 8; ++nt) {
                    uint32_t b0 = __float_as_uint(vb[nt*8]);
                    uint32_t b1 = __float_as_uint(vb[nt*8 + 4*QP]);
                    mma_tf32(acc[nt][0], acc[nt][1], acc[nt][2], acc[nt][3],
                             a0, a1, a2, a3, b0, b1);
                }
            }
        }
        __syncthreads();
        buf ^= 1;
    }

    // ---- epilogue: normalize, round to tf32, store ----
    {
        const float l0 = 1.0f / sL[wm+gid];
        const float l1 = 1.0f / sL[wm+gid+8];
        float* o0 = O + ((size_t)(b*NS + qt*FQT + wm + gid))*QDIM + h*HD + pn + 2*tig;
        float* o1 = o0 + (size_t)8*QDIM;
        #pragma unroll
        for (int nt = 0; nt < 8; ++nt) {
            *(float2*)(o0 + nt*8) = make_float2(rna_tf32(acc[nt][0]*l0), rna_tf32(acc[nt][1]*l0));
            *(float2*)(o1 + nt*8) = make_float2(rna_tf32(acc[nt][2]*l1), rna_tf32(acc[nt][3]*l1));
        }
    }
}

// ---------------------------------------------------------------------------
// Launch
// ---------------------------------------------------------------------------
extern "C" void kernel_launch(void* const* d_in, const int* in_sizes, int n_in,
                              void* d_out, int out_size)
{
    const float* hidden = (const float*)d_in[0];
    const float* wq = (const float*)d_in[1];
    const float* wk = (const float*)d_in[2];
    const float* wv = (const float*)d_in[3];
    const float* wo = (const float*)d_in[4];
    float* out = (float*)d_out;

    float *q, *k, *v, *o, *h2, *wq2, *wk2, *wv2, *wo2, *qhi, *qlo, *khi, *klo;
    cudaGetSymbolAddress((void**)&q,  g_q);
    cudaGetSymbolAddress((void**)&k,  g_k);
    cudaGetSymbolAddress((void**)&v,  g_v);
    cudaGetSymbolAddress((void**)&o,  g_o);
    cudaGetSymbolAddress((void**)&h2, g_h);
    cudaGetSymbolAddress((void**)&wq2, g_wq);
    cudaGetSymbolAddress((void**)&wk2, g_wk);
    cudaGetSymbolAddress((void**)&wv2, g_wv);
    cudaGetSymbolAddress((void**)&wo2, g_wo);
    cudaGetSymbolAddress((void**)&qhi, g_qhi);
    cudaGetSymbolAddress((void**)&qlo, g_qlo);
    cudaGetSymbolAddress((void**)&khi, g_khi);
    cudaGetSymbolAddress((void**)&klo, g_klo);

    cudaFuncSetAttribute(gemm_tf32, cudaFuncAttributeMaxDynamicSharedMemorySize, GEMM_SMEM);
    cudaFuncSetAttribute(flash_mma, cudaFuncAttributeMaxDynamicSharedMemorySize, FLASH_SMEM);

    // tf32-RNA pre-rounding of GEMM operands
    {
        int n4;
        n4 = NM*NHID/4;    round_tf32_kernel<<<(n4+255)/256, 256>>>((const float4*)hidden, (float4*)h2,  n4);
        n4 = QDIM*NHID/4;  round_tf32_kernel<<<(n4+255)/256, 256>>>((const float4*)wq,     (float4*)wq2, n4);
        n4 = KVDIM*NHID/4; round_tf32_kernel<<<(n4+255)/256, 256>>>((const float4*)wk,     (float4*)wk2, n4);
        n4 = KVDIM*NHID/4; round_tf32_kernel<<<(n4+255)/256, 256>>>((const float4*)wv,     (float4*)wv2, n4);
        n4 = NHID*QDIM/4;  round_tf32_kernel<<<(n4+255)/256, 256>>>((const float4*)wo,     (float4*)wo2, n4);
    }

    rope_table_kernel<<<(NS * 64 + 255) / 256, 256>>>();

    // Projections
    gemm_tf32<<<dim3(QDIM/128,  NM/128), 256, GEMM_SMEM>>>(h2, wq2, q, QDIM,  NHID);
    gemm_tf32<<<dim3(KVDIM/128, NM/128), 256, GEMM_SMEM>>>(h2, wk2, k, KVDIM, NHID);
    gemm_tf32<<<dim3(KVDIM/128, NM/128), 256, GEMM_SMEM>>>(h2, wv2, v, KVDIM, NHID);

    rope_apply_kernel<<<(NM * NH  * 64) / 256, 256>>>(q, NH);
    rope_apply_kernel<<<(NM * NKV * 64) / 256, 256>>>(k, NKV);

    // hi/lo split for flash QK; round V for PV
    {
        int n4;
        n4 = NM*QDIM/4;  split_tf32_kernel<<<(n4+255)/256, 256>>>((const float4*)q, (float4*)qhi, (float4*)qlo, n4);
        n4 = NM*KVDIM/4; split_tf32_kernel<<<(n4+255)/256, 256>>>((const float4*)k, (float4*)khi, (float4*)klo, n4);
        n4 = NM*KVDIM/4; round_tf32_kernel<<<(n4+255)/256, 256>>>((const float4*)v, (float4*)v, n4);
    }

    // Flash attention (epilogue pre-rounds output to tf32)
    flash_mma<<<dim3(NS/FQT, NH, NB), 256, FLASH_SMEM>>>(qhi, qlo, khi, klo, v, o);

    // Output projection
    gemm_tf32<<<dim3(QDIM/128, NM/128), 256, GEMM_SMEM>>>(o, wo2, out, QDIM, NHID);
}